// round 14
// baseline (speedup 1.0000x reference)
#include <cuda_runtime.h>
#include <cuda_fp16.h>

#define BB   32      // batch
#define NN   2048    // input capsules
#define IL   32      // input capsule length
#define CC   32      // output capsules
#define LL   32      // output capsule length
#define KK   1024    // CC*LL
#define NCH1 148     // j-chunks for k1 (13-14 j each; 148x4 = 592 CTAs = 2 FULL waves)
#define PCH  37      // pass CTAs per b: 37*32 = 1184 = 4 FULL waves at 2 CTAs/SM

typedef unsigned long long ull;

// Scratch (device globals: allocation-free rule)
__device__ __half g_uh [(size_t)BB * NN * KK];    // 128 MB prediction tensor (fp16)
__device__ float  g_s0p[(size_t)BB * NCH1 * KK];  // s partials, round 0 (19 MB)
__device__ float  g_sp [(size_t)BB * PCH * KK];   // s partials, rounds 1/2 (~5 MB)
__device__ float  g_v0 [BB * KK];
__device__ float  g_v1 [BB * KK];

__device__ __forceinline__ void ffma2(ull& acc, ull a, ull b) {
    asm("fma.rn.f32x2 %0, %1, %2, %0;" : "+l"(acc) : "l"(a), "l"(b));
}
__device__ __forceinline__ void fadd2(ull& acc, ull a) {
    asm("add.rn.f32x2 %0, %1, %0;" : "+l"(acc) : "l"(a));
}
__device__ __forceinline__ float2 up2(ull v) {
    float2 f;
    asm("mov.b64 {%0, %1}, %2;" : "=f"(f.x), "=f"(f.y) : "l"(v));
    return f;
}
__device__ __forceinline__ ull splat(float v) {
    ull r;
    asm("mov.b64 %0, {%1, %1};" : "=l"(r) : "f"(v));
    return r;
}
__device__ __forceinline__ __half2 geth2(const uint4& v, int p) {
    unsigned u = (&v.x)[p];
    return *reinterpret_cast<const __half2*>(&u);
}

// K1 (unchanged from the 104.5us round-12 version): u[b,j,k] =
// sum_i x[b,j,i]*W[j,i,k]; s0 partial = sum_j u / 32. Warp-private cp.async
// W pipelines (5-stage ring, depth-4), exact 2-wave grid (148x4), W tagged
// L2::evict_first, x staged transposed/padded, FFMA2 inner loop.
__global__ void __launch_bounds__(256, 2)
k1(const float* __restrict__ x, const float* __restrict__ Wt) {
    const int w     = threadIdx.x >> 5;    // warp 0..7 -> k-slice [w*32, w*32+32)
    const int lane  = threadIdx.x & 31;
    const int kgl   = lane & 7;            // 4-k group within warp slice
    const int bg    = lane >> 3;           // 0..3 -> 8 b's
    const int chunk = blockIdx.x;          // 0..147
    const int kq    = blockIdx.y;          // 0..3
    const int j0    = (chunk * NN) / NCH1;
    const int j1    = ((chunk + 1) * NN) / NCH1;
    const int nst   = 4 * (j1 - j0);       // 52 or 56 stages

    __shared__ __align__(16) float wbuf[5][8][256];   // 40 KB W ring (warp-sliced)
    __shared__ __align__(16) float xs[2][32][36];     // 9 KB x (transposed, padded)

    const int cr = lane >> 2;
    const int cc = (lane & 3) * 8;

    ull pol;   // read-once W: evict-first so u stays resident in L2
    asm("createpolicy.fractional.L2::evict_first.b64 %0, 1.0;" : "=l"(pol));

    auto issue_stage = [&](int g) {
        const int jg = j0 + (g >> 2);
        const int ibase = (g & 3) * 8;
        const float* src = Wt + (size_t)jg * (IL * KK) + (size_t)(ibase + cr) * KK
                         + kq * 256 + w * 32 + cc;
        unsigned dst = (unsigned)__cvta_generic_to_shared(&wbuf[g % 5][cr][w * 32 + cc]);
        asm volatile(
            "cp.async.cg.shared.global.L2::cache_hint [%0], [%1], 16, %2;\n\t"
            "cp.async.cg.shared.global.L2::cache_hint [%3], [%4], 16, %2;"
            :: "r"(dst), "l"(src), "l"(pol), "r"(dst + 16), "l"(src + 4) : "memory");
    };

    ull acc[4][4], s0[4][4];               // [k][b-pair] f32x2
#pragma unroll
    for (int k = 0; k < 4; k++)
#pragma unroll
        for (int bp = 0; bp < 4; bp++) { acc[k][bp] = 0ull; s0[k][bp] = 0ull; }

#pragma unroll
    for (int pg = 0; pg < 4; pg++) {
        issue_stage(pg);
        asm volatile("cp.async.commit_group;" ::: "memory");
    }

    for (int g = 0; g < nst; g++) {        // stages: j-count x 4 i-blocks of 8
        if ((g & 7) == 0) {
            __syncthreads();               // all warps done reading xs slots
            const int jp = j0 + (g >> 2);
#pragma unroll
            for (int r = 0; r < 8; r++) {
                int idx = threadIdx.x + 256 * r;
                int jl = idx >> 10, rem = idx & 1023;
                int b = rem >> 5, i = rem & 31;
                int jj = jp + jl; if (jj > NN - 1) jj = NN - 1;   // clamp (tail pair)
                xs[jl][i][b] = x[((size_t)b * NN + jj) * IL + i];
            }
            __syncthreads();
        }

        asm volatile("cp.async.wait_group 3;" ::: "memory");
        __syncwarp();

        const int jl = (g >> 2) & 1;
        const int ib = (g & 3) * 8;
        const float (*wb)[256] = wbuf[g % 5];
#pragma unroll
        for (int ii = 0; ii < 8; ii++) {
            float4 wv = *reinterpret_cast<const float4*>(&wb[ii][w * 32 + kgl * 4]);
            ull ws0 = splat(wv.x), ws1 = splat(wv.y), ws2 = splat(wv.z), ws3 = splat(wv.w);
            ulonglong2 xu0 = *reinterpret_cast<const ulonglong2*>(&xs[jl][ib + ii][bg * 8]);
            ulonglong2 xu1 = *reinterpret_cast<const ulonglong2*>(&xs[jl][ib + ii][bg * 8 + 4]);
            ffma2(acc[0][0], ws0, xu0.x); ffma2(acc[0][1], ws0, xu0.y);
            ffma2(acc[0][2], ws0, xu1.x); ffma2(acc[0][3], ws0, xu1.y);
            ffma2(acc[1][0], ws1, xu0.x); ffma2(acc[1][1], ws1, xu0.y);
            ffma2(acc[1][2], ws1, xu1.x); ffma2(acc[1][3], ws1, xu1.y);
            ffma2(acc[2][0], ws2, xu0.x); ffma2(acc[2][1], ws2, xu0.y);
            ffma2(acc[2][2], ws2, xu1.x); ffma2(acc[2][3], ws2, xu1.y);
            ffma2(acc[3][0], ws3, xu0.x); ffma2(acc[3][1], ws3, xu0.y);
            ffma2(acc[3][2], ws3, xu1.x); ffma2(acc[3][3], ws3, xu1.y);
        }

        if ((g & 3) == 3) {
            const int jg = j0 + (g >> 2);
            const size_t kb = (size_t)kq * 256 + (size_t)(w * 32 + kgl * 4);
#pragma unroll
            for (int bp = 0; bp < 4; bp++) {
                float2 f0 = up2(acc[0][bp]), f1 = up2(acc[1][bp]);
                float2 f2 = up2(acc[2][bp]), f3 = up2(acc[3][bp]);
                const int be = bg * 8 + bp * 2;
                __half2 h0 = __floats2half2_rn(f0.x, f1.x);
                __half2 h1 = __floats2half2_rn(f2.x, f3.x);
                uint2 pk;
                pk.x = *reinterpret_cast<unsigned*>(&h0);
                pk.y = *reinterpret_cast<unsigned*>(&h1);
                *reinterpret_cast<uint2*>(g_uh + ((size_t)be * NN + jg) * KK + kb) = pk;
                h0 = __floats2half2_rn(f0.y, f1.y);
                h1 = __floats2half2_rn(f2.y, f3.y);
                pk.x = *reinterpret_cast<unsigned*>(&h0);
                pk.y = *reinterpret_cast<unsigned*>(&h1);
                *reinterpret_cast<uint2*>(g_uh + ((size_t)(be + 1) * NN + jg) * KK + kb) = pk;
#pragma unroll
                for (int k = 0; k < 4; k++) {
                    fadd2(s0[k][bp], acc[k][bp]);
                    acc[k][bp] = 0ull;
                }
            }
        }

        if (g + 4 < nst) issue_stage(g + 4);
        asm volatile("cp.async.commit_group;" ::: "memory");
    }

    const float scl = 1.0f / 32.0f;
    const size_t kb = (size_t)kq * 256 + (size_t)(w * 32 + kgl * 4);
#pragma unroll
    for (int bp = 0; bp < 4; bp++) {
        float2 f0 = up2(s0[0][bp]), f1 = up2(s0[1][bp]);
        float2 f2 = up2(s0[2][bp]), f3 = up2(s0[3][bp]);
        const int be = bg * 8 + bp * 2;
        *reinterpret_cast<float4*>(g_s0p + ((size_t)be * NCH1 + chunk) * KK + kb) =
            make_float4(f0.x * scl, f1.x * scl, f2.x * scl, f3.x * scl);
        *reinterpret_cast<float4*>(g_s0p + ((size_t)(be + 1) * NCH1 + chunk) * KK + kb) =
            make_float4(f0.y * scl, f1.y * scl, f2.y * scl, f3.y * scl);
    }
}

// Routing pass v6 = v5 body (no-max softmax, FFMA2 accumulation) with an
// EXACT-WAVE dynamic work split: pair-space [0,1024) per b (pair p = rows
// 2p, 2p+1) divided over 37 CTAs (27-28 pairs) and 8 warps (3-4 pairs,
// always >=1). Grid 37x32 = 1184 CTAs = exactly 4 full waves at 2/SM
// (v5's 32x32 grid ran 3.46 waves -> idle tail).
template <int NP>
__global__ void __launch_bounds__(256, 2)
k_pass(const float* __restrict__ vin0, const float* __restrict__ vin1,
       float* __restrict__ sp) {
    const int b = blockIdx.y;
    const int w = threadIdx.x >> 5;
    const int t = threadIdx.x & 31;

    __shared__ float red[8][1032];     // CTA reduction (16B-aligned rows)

    // v as half2 registers at the u k-mapping (NP==2 folds v0+v1)
    __half2 vh[16];
#pragma unroll
    for (int q = 0; q < 4; q++) {
        float4 a = *reinterpret_cast<const float4*>(vin0 + (size_t)b * KK + 8 * t + 256 * q);
        float4 c4 = *reinterpret_cast<const float4*>(vin0 + (size_t)b * KK + 8 * t + 256 * q + 4);
        if (NP == 2) {
            float4 a1 = *reinterpret_cast<const float4*>(vin1 + (size_t)b * KK + 8 * t + 256 * q);
            float4 c1 = *reinterpret_cast<const float4*>(vin1 + (size_t)b * KK + 8 * t + 256 * q + 4);
            a.x += a1.x; a.y += a1.y; a.z += a1.z; a.w += a1.w;
            c4.x += c1.x; c4.y += c1.y; c4.z += c1.z; c4.w += c1.w;
        }
        vh[q * 4 + 0] = __floats2half2_rn(a.x, a.y);
        vh[q * 4 + 1] = __floats2half2_rn(a.z, a.w);
        vh[q * 4 + 2] = __floats2half2_rn(c4.x, c4.y);
        vh[q * 4 + 3] = __floats2half2_rn(c4.z, c4.w);
    }

    ull sacc2[16];                     // packed f32x2 s accumulators
#pragma unroll
    for (int l = 0; l < 16; l++) sacc2[l] = 0ull;

    // dynamic pair range for this CTA / warp
    const int p0  = (blockIdx.x * 1024) / PCH;
    const int p1  = ((blockIdx.x + 1) * 1024) / PCH;
    const int cnt = p1 - p0;
    const int pw0 = p0 + (w * cnt) / 8;
    const int pw1 = p0 + ((w + 1) * cnt) / 8;

    const uint4* up = reinterpret_cast<const uint4*>(g_uh + (size_t)b * NN * KK);

    uint4 raw0[4], raw1[4];
#pragma unroll
    for (int q = 0; q < 4; q++) raw0[q] = up[(size_t)(2 * pw0) * 128 + q * 32 + t];
#pragma unroll
    for (int q = 0; q < 4; q++) raw1[q] = up[(size_t)(2 * pw0 + 1) * 128 + q * 32 + t];

    for (int p = pw0; p < pw1; p++) {
        // free raw0 early: copy, then prefetch next pair's row0 into it
        uint4 cpy0[4];
#pragma unroll
        for (int q = 0; q < 4; q++) cpy0[q] = raw0[q];
        if (p + 1 < pw1) {
#pragma unroll
            for (int q = 0; q < 4; q++)
                raw0[q] = up[(size_t)(2 * p + 2) * 128 + q * 32 + t];
        }

        // logits for both rows (HFMA2 dot), interleaved
        float d0[4], d1[4];
#pragma unroll
        for (int q = 0; q < 4; q++) {
            __half2 a0 = __float2half2_rn(0.f), a1 = __float2half2_rn(0.f);
#pragma unroll
            for (int pp = 0; pp < 4; pp++) {
                a0 = __hfma2(geth2(cpy0[q], pp), vh[q * 4 + pp], a0);
                a1 = __hfma2(geth2(raw1[q], pp), vh[q * 4 + pp], a1);
            }
            float2 f0 = __half22float2(a0), f1 = __half22float2(a1);
            d0[q] = f0.x + f0.y;
            d1[q] = f1.x + f1.y;
            d0[q] += __shfl_xor_sync(0xffffffffu, d0[q], 1);
            d1[q] += __shfl_xor_sync(0xffffffffu, d1[q], 1);
            d0[q] += __shfl_xor_sync(0xffffffffu, d0[q], 2);
            d1[q] += __shfl_xor_sync(0xffffffffu, d1[q], 2);
        }

        // softmax over 32 capsules WITHOUT max-subtraction (|d| is O(1))
        float ce0[4], ce1[4];
#pragma unroll
        for (int q = 0; q < 4; q++) {
            ce0[q] = __expf(d0[q]);
            ce1[q] = __expf(d1[q]);
        }
        float Z0 = (ce0[0] + ce0[1]) + (ce0[2] + ce0[3]);
        float Z1 = (ce1[0] + ce1[1]) + (ce1[2] + ce1[3]);
        Z0 += __shfl_xor_sync(0xffffffffu, Z0, 4);
        Z1 += __shfl_xor_sync(0xffffffffu, Z1, 4);
        Z0 += __shfl_xor_sync(0xffffffffu, Z0, 8);
        Z1 += __shfl_xor_sync(0xffffffffu, Z1, 8);
        Z0 += __shfl_xor_sync(0xffffffffu, Z0, 16);
        Z1 += __shfl_xor_sync(0xffffffffu, Z1, 16);
        const float i0 = __fdividef(1.0f, Z0);
        const float i1 = __fdividef(1.0f, Z1);

        // accumulate both rows: coupling splat + packed FFMA2
#pragma unroll
        for (int q = 0; q < 4; q++) {
            ull cs0 = splat(ce0[q] * i0);
            ull cs1 = splat(ce1[q] * i1);
#pragma unroll
            for (int pp = 0; pp < 4; pp++) {
                float2 f = __half22float2(geth2(cpy0[q], pp));
                ffma2(sacc2[q * 4 + pp], cs0, *reinterpret_cast<ull*>(&f));
                f = __half22float2(geth2(raw1[q], pp));
                ffma2(sacc2[q * 4 + pp], cs1, *reinterpret_cast<ull*>(&f));
            }
        }

        // raw1 now free: prefetch next pair's row1
        if (p + 1 < pw1) {
#pragma unroll
            for (int q = 0; q < 4; q++)
                raw1[q] = up[(size_t)(2 * p + 3) * 128 + q * 32 + t];
        }
    }

    // CTA reduction across the 8 warps (natural k layout)
#pragma unroll
    for (int q = 0; q < 4; q++) {
        float2 pr0 = up2(sacc2[q * 4 + 0]), pr1 = up2(sacc2[q * 4 + 1]);
        float2 pr2 = up2(sacc2[q * 4 + 2]), pr3 = up2(sacc2[q * 4 + 3]);
        *reinterpret_cast<float4*>(&red[w][8 * t + 256 * q])     =
            make_float4(pr0.x, pr0.y, pr1.x, pr1.y);
        *reinterpret_cast<float4*>(&red[w][8 * t + 256 * q + 4]) =
            make_float4(pr2.x, pr2.y, pr3.x, pr3.y);
    }
    __syncthreads();

    float4 s = make_float4(0.f, 0.f, 0.f, 0.f);
#pragma unroll
    for (int ww = 0; ww < 8; ww++) {
        float4 p = *reinterpret_cast<const float4*>(&red[ww][4 * threadIdx.x]);
        s.x += p.x; s.y += p.y; s.z += p.z; s.w += p.w;
    }
    *reinterpret_cast<float4*>(sp + ((size_t)b * PCH + blockIdx.x) * KK + 4 * threadIdx.x) = s;
}

// Finalize: reduce NCH chunk partials + biases, squash -> v.
// One CTA (8 warps) per (b,c) for memory-level parallelism on the reduction.
template <int NCH>
__global__ void __launch_bounds__(256)
k_fin(const float* __restrict__ sp, const float* __restrict__ biases,
      float* __restrict__ vout) {
    const int bc = blockIdx.x;
    const int b = bc >> 5, c = bc & 31;
    const int w = threadIdx.x >> 5, lane = threadIdx.x & 31;

    float s = 0.f;
    const float* p = sp + (size_t)b * NCH * KK + c * LL + lane;
#pragma unroll 8
    for (int n = w; n < NCH; n += 8) s += p[(size_t)n * KK];

    __shared__ float red[8][32];
    red[w][lane] = s;
    __syncthreads();

    if (w == 0) {
        float v = biases[c * LL + lane];
#pragma unroll
        for (int ww = 0; ww < 8; ww++) v += red[ww][lane];
        float n2 = v * v;
#pragma unroll
        for (int o = 16; o; o >>= 1) n2 += __shfl_xor_sync(0xffffffffu, n2, o);
        const float nn = sqrtf(n2);
        const float f = n2 / (1.0f + n2) / (nn + 1e-7f);   // squash factor
        vout[(size_t)b * KK + c * LL + lane] = f * v;
    }
}

extern "C" void kernel_launch(void* const* d_in, const int* in_sizes, int n_in,
                              void* d_out, int out_size) {
    const float* x      = (const float*)d_in[0];  // [32,8,8,32,32] = [B,N,iL]
    const float* Wt     = (const float*)d_in[1];  // [2048,32,1024]
    const float* biases = (const float*)d_in[2];  // [32,32]
    float* out = (float*)d_out;                   // [32,32,32]

    float *s0p, *sp, *v0, *v1;
    cudaGetSymbolAddress((void**)&s0p, g_s0p);
    cudaGetSymbolAddress((void**)&sp,  g_sp);
    cudaGetSymbolAddress((void**)&v0,  g_v0);
    cudaGetSymbolAddress((void**)&v1,  g_v1);

    // 6 launches, no dummies (~2us saved per removed launch per replay).
    k1<<<dim3(NCH1, 4), 256>>>(x, Wt);                   // 0
    k_fin<NCH1><<<BB * CC, 256>>>(s0p, biases, v0);      // 1
    k_pass<1><<<dim3(PCH, BB), 256>>>(v0, v0, sp);       // 2
    k_fin<PCH><<<BB * CC, 256>>>(sp, biases, v1);        // 3
    k_pass<2><<<dim3(PCH, BB), 256>>>(v0, v1, sp);       // 4
    k_fin<PCH><<<BB * CC, 256>>>(sp, biases, out);       // 5
}

// round 15
// speedup vs baseline: 1.0336x; 1.0336x over previous
#include <cuda_runtime.h>
#include <cuda_fp16.h>

#define BB   32      // batch
#define NN   2048    // input capsules
#define IL   32      // input capsule length
#define CC   32      // output capsules
#define LL   32      // output capsule length
#define KK   1024    // CC*LL
#define NCH1 148     // j-chunks for k1 (13-14 j each; 148x4 = 592 CTAs = 2 FULL waves)
#define PCH  32      // pass CTAs per b (64 j each; every warp exactly 8 j — balanced)

typedef unsigned long long ull;

// Scratch (device globals: allocation-free rule)
__device__ __half g_uh [(size_t)BB * NN * KK];    // 128 MB prediction tensor (fp16)
__device__ float  g_s0p[(size_t)BB * NCH1 * KK];  // s partials, round 0 (19 MB)
__device__ float  g_sp [(size_t)BB * PCH * KK];   // s partials, rounds 1/2 (4 MB)
__device__ float  g_v0 [BB * KK];
__device__ float  g_v1 [BB * KK];

__device__ __forceinline__ void ffma2(ull& acc, ull a, ull b) {
    asm("fma.rn.f32x2 %0, %1, %2, %0;" : "+l"(acc) : "l"(a), "l"(b));
}
__device__ __forceinline__ void fadd2(ull& acc, ull a) {
    asm("add.rn.f32x2 %0, %1, %0;" : "+l"(acc) : "l"(a));
}
__device__ __forceinline__ float2 up2(ull v) {
    float2 f;
    asm("mov.b64 {%0, %1}, %2;" : "=f"(f.x), "=f"(f.y) : "l"(v));
    return f;
}
__device__ __forceinline__ ull splat(float v) {
    ull r;
    asm("mov.b64 %0, {%1, %1};" : "=l"(r) : "f"(v));
    return r;
}
__device__ __forceinline__ __half2 geth2(const uint4& v, int p) {
    unsigned u = (&v.x)[p];
    return *reinterpret_cast<const __half2*>(&u);
}

// K1 (the proven 104.5us version): u[b,j,k] = sum_i x[b,j,i]*W[j,i,k];
// s0 partial = sum_j u / 32. Warp-private cp.async W pipelines (5-stage
// ring, depth-4), exact 2-wave grid (148x4), W tagged L2::evict_first,
// x staged transposed/padded, FFMA2 inner loop.
__global__ void __launch_bounds__(256, 2)
k1(const float* __restrict__ x, const float* __restrict__ Wt) {
    const int w     = threadIdx.x >> 5;    // warp 0..7 -> k-slice [w*32, w*32+32)
    const int lane  = threadIdx.x & 31;
    const int kgl   = lane & 7;            // 4-k group within warp slice
    const int bg    = lane >> 3;           // 0..3 -> 8 b's
    const int chunk = blockIdx.x;          // 0..147
    const int kq    = blockIdx.y;          // 0..3
    const int j0    = (chunk * NN) / NCH1;
    const int j1    = ((chunk + 1) * NN) / NCH1;
    const int nst   = 4 * (j1 - j0);       // 52 or 56 stages

    __shared__ __align__(16) float wbuf[5][8][256];   // 40 KB W ring (warp-sliced)
    __shared__ __align__(16) float xs[2][32][36];     // 9 KB x (transposed, padded)

    const int cr = lane >> 2;
    const int cc = (lane & 3) * 8;

    ull pol;   // read-once W: evict-first so u stays resident in L2
    asm("createpolicy.fractional.L2::evict_first.b64 %0, 1.0;" : "=l"(pol));

    auto issue_stage = [&](int g) {
        const int jg = j0 + (g >> 2);
        const int ibase = (g & 3) * 8;
        const float* src = Wt + (size_t)jg * (IL * KK) + (size_t)(ibase + cr) * KK
                         + kq * 256 + w * 32 + cc;
        unsigned dst = (unsigned)__cvta_generic_to_shared(&wbuf[g % 5][cr][w * 32 + cc]);
        asm volatile(
            "cp.async.cg.shared.global.L2::cache_hint [%0], [%1], 16, %2;\n\t"
            "cp.async.cg.shared.global.L2::cache_hint [%3], [%4], 16, %2;"
            :: "r"(dst), "l"(src), "l"(pol), "r"(dst + 16), "l"(src + 4) : "memory");
    };

    ull acc[4][4], s0[4][4];               // [k][b-pair] f32x2
#pragma unroll
    for (int k = 0; k < 4; k++)
#pragma unroll
        for (int bp = 0; bp < 4; bp++) { acc[k][bp] = 0ull; s0[k][bp] = 0ull; }

#pragma unroll
    for (int pg = 0; pg < 4; pg++) {
        issue_stage(pg);
        asm volatile("cp.async.commit_group;" ::: "memory");
    }

    for (int g = 0; g < nst; g++) {        // stages: j-count x 4 i-blocks of 8
        if ((g & 7) == 0) {
            __syncthreads();               // all warps done reading xs slots
            const int jp = j0 + (g >> 2);
#pragma unroll
            for (int r = 0; r < 8; r++) {
                int idx = threadIdx.x + 256 * r;
                int jl = idx >> 10, rem = idx & 1023;
                int b = rem >> 5, i = rem & 31;
                int jj = jp + jl; if (jj > NN - 1) jj = NN - 1;   // clamp (tail pair)
                xs[jl][i][b] = x[((size_t)b * NN + jj) * IL + i];
            }
            __syncthreads();
        }

        asm volatile("cp.async.wait_group 3;" ::: "memory");
        __syncwarp();

        const int jl = (g >> 2) & 1;
        const int ib = (g & 3) * 8;
        const float (*wb)[256] = wbuf[g % 5];
#pragma unroll
        for (int ii = 0; ii < 8; ii++) {
            float4 wv = *reinterpret_cast<const float4*>(&wb[ii][w * 32 + kgl * 4]);
            ull ws0 = splat(wv.x), ws1 = splat(wv.y), ws2 = splat(wv.z), ws3 = splat(wv.w);
            ulonglong2 xu0 = *reinterpret_cast<const ulonglong2*>(&xs[jl][ib + ii][bg * 8]);
            ulonglong2 xu1 = *reinterpret_cast<const ulonglong2*>(&xs[jl][ib + ii][bg * 8 + 4]);
            ffma2(acc[0][0], ws0, xu0.x); ffma2(acc[0][1], ws0, xu0.y);
            ffma2(acc[0][2], ws0, xu1.x); ffma2(acc[0][3], ws0, xu1.y);
            ffma2(acc[1][0], ws1, xu0.x); ffma2(acc[1][1], ws1, xu0.y);
            ffma2(acc[1][2], ws1, xu1.x); ffma2(acc[1][3], ws1, xu1.y);
            ffma2(acc[2][0], ws2, xu0.x); ffma2(acc[2][1], ws2, xu0.y);
            ffma2(acc[2][2], ws2, xu1.x); ffma2(acc[2][3], ws2, xu1.y);
            ffma2(acc[3][0], ws3, xu0.x); ffma2(acc[3][1], ws3, xu0.y);
            ffma2(acc[3][2], ws3, xu1.x); ffma2(acc[3][3], ws3, xu1.y);
        }

        if ((g & 3) == 3) {
            const int jg = j0 + (g >> 2);
            const size_t kb = (size_t)kq * 256 + (size_t)(w * 32 + kgl * 4);
#pragma unroll
            for (int bp = 0; bp < 4; bp++) {
                float2 f0 = up2(acc[0][bp]), f1 = up2(acc[1][bp]);
                float2 f2 = up2(acc[2][bp]), f3 = up2(acc[3][bp]);
                const int be = bg * 8 + bp * 2;
                __half2 h0 = __floats2half2_rn(f0.x, f1.x);
                __half2 h1 = __floats2half2_rn(f2.x, f3.x);
                uint2 pk;
                pk.x = *reinterpret_cast<unsigned*>(&h0);
                pk.y = *reinterpret_cast<unsigned*>(&h1);
                *reinterpret_cast<uint2*>(g_uh + ((size_t)be * NN + jg) * KK + kb) = pk;
                h0 = __floats2half2_rn(f0.y, f1.y);
                h1 = __floats2half2_rn(f2.y, f3.y);
                pk.x = *reinterpret_cast<unsigned*>(&h0);
                pk.y = *reinterpret_cast<unsigned*>(&h1);
                *reinterpret_cast<uint2*>(g_uh + ((size_t)(be + 1) * NN + jg) * KK + kb) = pk;
#pragma unroll
                for (int k = 0; k < 4; k++) {
                    fadd2(s0[k][bp], acc[k][bp]);
                    acc[k][bp] = 0ull;
                }
            }
        }

        if (g + 4 < nst) issue_stage(g + 4);
        asm volatile("cp.async.commit_group;" ::: "memory");
    }

    const float scl = 1.0f / 32.0f;
    const size_t kb = (size_t)kq * 256 + (size_t)(w * 32 + kgl * 4);
#pragma unroll
    for (int bp = 0; bp < 4; bp++) {
        float2 f0 = up2(s0[0][bp]), f1 = up2(s0[1][bp]);
        float2 f2 = up2(s0[2][bp]), f3 = up2(s0[3][bp]);
        const int be = bg * 8 + bp * 2;
        *reinterpret_cast<float4*>(g_s0p + ((size_t)be * NCH1 + chunk) * KK + kb) =
            make_float4(f0.x * scl, f1.x * scl, f2.x * scl, f3.x * scl);
        *reinterpret_cast<float4*>(g_s0p + ((size_t)(be + 1) * NCH1 + chunk) * KK + kb) =
            make_float4(f0.y * scl, f1.y * scl, f2.y * scl, f3.y * scl);
    }
}

// Routing pass (round-13 version: PCH=32, every warp exactly 8 j — balanced;
// no-max softmax, FFMA2 accumulation). Lane t's uint4 group q covers
// k = 8t+256q+e, all in capsule c_q = (t>>2)+8q; quad shfl completes each
// logit, shfl xor 4/8/16 spans the 32 capsules.
template <int NP>
__global__ void __launch_bounds__(256, 2)
k_pass(const float* __restrict__ vin0, const float* __restrict__ vin1,
       float* __restrict__ sp) {
    const int b = blockIdx.y;
    const int w = threadIdx.x >> 5;
    const int t = threadIdx.x & 31;

    __shared__ float red[8][1032];     // CTA reduction (16B-aligned rows)

    // v as half2 registers at the u k-mapping (NP==2 folds v0+v1)
    __half2 vh[16];
#pragma unroll
    for (int q = 0; q < 4; q++) {
        float4 a = *reinterpret_cast<const float4*>(vin0 + (size_t)b * KK + 8 * t + 256 * q);
        float4 c4 = *reinterpret_cast<const float4*>(vin0 + (size_t)b * KK + 8 * t + 256 * q + 4);
        if (NP == 2) {
            float4 a1 = *reinterpret_cast<const float4*>(vin1 + (size_t)b * KK + 8 * t + 256 * q);
            float4 c1 = *reinterpret_cast<const float4*>(vin1 + (size_t)b * KK + 8 * t + 256 * q + 4);
            a.x += a1.x; a.y += a1.y; a.z += a1.z; a.w += a1.w;
            c4.x += c1.x; c4.y += c1.y; c4.z += c1.z; c4.w += c1.w;
        }
        vh[q * 4 + 0] = __floats2half2_rn(a.x, a.y);
        vh[q * 4 + 1] = __floats2half2_rn(a.z, a.w);
        vh[q * 4 + 2] = __floats2half2_rn(c4.x, c4.y);
        vh[q * 4 + 3] = __floats2half2_rn(c4.z, c4.w);
    }

    ull sacc2[16];                     // packed f32x2 s accumulators
#pragma unroll
    for (int l = 0; l < 16; l++) sacc2[l] = 0ull;

    const int jbase = blockIdx.x * 64 + w * 8;   // 8 warps x 8 j = 64 j / CTA
    const uint4* up = reinterpret_cast<const uint4*>(g_uh + ((size_t)b * NN + jbase) * KK);

    uint4 raw0[4], raw1[4];
#pragma unroll
    for (int q = 0; q < 4; q++) raw0[q] = up[q * 32 + t];          // j0
#pragma unroll
    for (int q = 0; q < 4; q++) raw1[q] = up[128 + q * 32 + t];    // j1

    for (int jb = 0; jb < 8; jb += 2) {
        // free raw0 early: copy, then prefetch j+2 into it
        uint4 cpy0[4];
#pragma unroll
        for (int q = 0; q < 4; q++) cpy0[q] = raw0[q];
        if (jb + 2 < 8) {
#pragma unroll
            for (int q = 0; q < 4; q++) raw0[q] = up[(jb + 2) * 128 + q * 32 + t];
        }

        // logits for both rows (HFMA2 dot), interleaved
        float d0[4], d1[4];
#pragma unroll
        for (int q = 0; q < 4; q++) {
            __half2 a0 = __float2half2_rn(0.f), a1 = __float2half2_rn(0.f);
#pragma unroll
            for (int p = 0; p < 4; p++) {
                a0 = __hfma2(geth2(cpy0[q], p), vh[q * 4 + p], a0);
                a1 = __hfma2(geth2(raw1[q], p), vh[q * 4 + p], a1);
            }
            float2 f0 = __half22float2(a0), f1 = __half22float2(a1);
            d0[q] = f0.x + f0.y;
            d1[q] = f1.x + f1.y;
            d0[q] += __shfl_xor_sync(0xffffffffu, d0[q], 1);
            d1[q] += __shfl_xor_sync(0xffffffffu, d1[q], 1);
            d0[q] += __shfl_xor_sync(0xffffffffu, d0[q], 2);
            d1[q] += __shfl_xor_sync(0xffffffffu, d1[q], 2);
        }

        // softmax over 32 capsules WITHOUT max-subtraction (|d| is O(1))
        float ce0[4], ce1[4];
#pragma unroll
        for (int q = 0; q < 4; q++) {
            ce0[q] = __expf(d0[q]);
            ce1[q] = __expf(d1[q]);
        }
        float Z0 = (ce0[0] + ce0[1]) + (ce0[2] + ce0[3]);
        float Z1 = (ce1[0] + ce1[1]) + (ce1[2] + ce1[3]);
        Z0 += __shfl_xor_sync(0xffffffffu, Z0, 4);
        Z1 += __shfl_xor_sync(0xffffffffu, Z1, 4);
        Z0 += __shfl_xor_sync(0xffffffffu, Z0, 8);
        Z1 += __shfl_xor_sync(0xffffffffu, Z1, 8);
        Z0 += __shfl_xor_sync(0xffffffffu, Z0, 16);
        Z1 += __shfl_xor_sync(0xffffffffu, Z1, 16);
        const float i0 = __fdividef(1.0f, Z0);
        const float i1 = __fdividef(1.0f, Z1);

        // accumulate both rows: coupling splat + packed FFMA2
#pragma unroll
        for (int q = 0; q < 4; q++) {
            ull cs0 = splat(ce0[q] * i0);
            ull cs1 = splat(ce1[q] * i1);
#pragma unroll
            for (int p = 0; p < 4; p++) {
                float2 f = __half22float2(geth2(cpy0[q], p));
                ffma2(sacc2[q * 4 + p], cs0, *reinterpret_cast<ull*>(&f));
                f = __half22float2(geth2(raw1[q], p));
                ffma2(sacc2[q * 4 + p], cs1, *reinterpret_cast<ull*>(&f));
            }
        }

        // raw1 now free: prefetch j+3
        if (jb + 3 < 8) {
#pragma unroll
            for (int q = 0; q < 4; q++) raw1[q] = up[(jb + 3) * 128 + q * 32 + t];
        }
    }

    // CTA reduction across the 8 warps (natural k layout)
#pragma unroll
    for (int q = 0; q < 4; q++) {
        float2 p0 = up2(sacc2[q * 4 + 0]), p1 = up2(sacc2[q * 4 + 1]);
        float2 p2 = up2(sacc2[q * 4 + 2]), p3 = up2(sacc2[q * 4 + 3]);
        *reinterpret_cast<float4*>(&red[w][8 * t + 256 * q])     =
            make_float4(p0.x, p0.y, p1.x, p1.y);
        *reinterpret_cast<float4*>(&red[w][8 * t + 256 * q + 4]) =
            make_float4(p2.x, p2.y, p3.x, p3.y);
    }
    __syncthreads();

    float4 s = make_float4(0.f, 0.f, 0.f, 0.f);
#pragma unroll
    for (int ww = 0; ww < 8; ww++) {
        float4 p = *reinterpret_cast<const float4*>(&red[ww][4 * threadIdx.x]);
        s.x += p.x; s.y += p.y; s.z += p.z; s.w += p.w;
    }
    *reinterpret_cast<float4*>(sp + ((size_t)b * PCH + blockIdx.x) * KK + 4 * threadIdx.x) = s;
}

// Finalize: reduce NCH chunk partials + biases, squash -> v.
// One CTA (8 warps) per (b,c) for memory-level parallelism on the reduction.
template <int NCH>
__global__ void __launch_bounds__(256)
k_fin(const float* __restrict__ sp, const float* __restrict__ biases,
      float* __restrict__ vout) {
    const int bc = blockIdx.x;
    const int b = bc >> 5, c = bc & 31;
    const int w = threadIdx.x >> 5, lane = threadIdx.x & 31;

    float s = 0.f;
    const float* p = sp + (size_t)b * NCH * KK + c * LL + lane;
#pragma unroll 8
    for (int n = w; n < NCH; n += 8) s += p[(size_t)n * KK];

    __shared__ float red[8][32];
    red[w][lane] = s;
    __syncthreads();

    if (w == 0) {
        float v = biases[c * LL + lane];
#pragma unroll
        for (int ww = 0; ww < 8; ww++) v += red[ww][lane];
        float n2 = v * v;
#pragma unroll
        for (int o = 16; o; o >>= 1) n2 += __shfl_xor_sync(0xffffffffu, n2, o);
        const float nn = sqrtf(n2);
        const float f = n2 / (1.0f + n2) / (nn + 1e-7f);   // squash factor
        vout[(size_t)b * KK + c * LL + lane] = f * v;
    }
}

extern "C" void kernel_launch(void* const* d_in, const int* in_sizes, int n_in,
                              void* d_out, int out_size) {
    const float* x      = (const float*)d_in[0];  // [32,8,8,32,32] = [B,N,iL]
    const float* Wt     = (const float*)d_in[1];  // [2048,32,1024]
    const float* biases = (const float*)d_in[2];  // [32,32]
    float* out = (float*)d_out;                   // [32,32,32]

    float *s0p, *sp, *v0, *v1;
    cudaGetSymbolAddress((void**)&s0p, g_s0p);
    cudaGetSymbolAddress((void**)&sp,  g_sp);
    cudaGetSymbolAddress((void**)&v0,  g_v0);
    cudaGetSymbolAddress((void**)&v1,  g_v1);

    // 6 launches, no dummies; balanced PCH=32 passes.
    k1<<<dim3(NCH1, 4), 256>>>(x, Wt);                   // 0
    k_fin<NCH1><<<BB * CC, 256>>>(s0p, biases, v0);      // 1
    k_pass<1><<<dim3(PCH, BB), 256>>>(v0, v0, sp);       // 2
    k_fin<PCH><<<BB * CC, 256>>>(sp, biases, v1);        // 3
    k_pass<2><<<dim3(PCH, BB), 256>>>(v0, v1, sp);       // 4
    k_fin<PCH><<<BB * CC, 256>>>(sp, biases, out);       // 5
}

// round 16
// speedup vs baseline: 1.0461x; 1.0121x over previous
#include <cuda_runtime.h>
#include <cuda_fp16.h>

#define BB   32      // batch
#define NN   2048    // input capsules
#define IL   32      // input capsule length
#define CC   32      // output capsules
#define LL   32      // output capsule length
#define KK   1024    // CC*LL
#define NCH1 148     // j-chunks for k1 (13-14 j each; 148x4 = 592 CTAs = 2 FULL waves)
#define PCH  32      // pass CTAs per b (64 j each; every warp exactly 8 j — balanced)

typedef unsigned long long ull;

// Scratch (device globals: allocation-free rule)
__device__ __half g_uh [(size_t)BB * NN * KK];    // 128 MB prediction tensor (fp16)
__device__ float  g_s0p[(size_t)BB * NCH1 * KK];  // s partials, round 0 (19 MB)
__device__ float  g_sp [(size_t)BB * PCH * KK];   // s partials, rounds 1/2 (4 MB)
__device__ float  g_v0 [BB * KK];
__device__ float  g_v1 [BB * KK];

__device__ __forceinline__ void ffma2(ull& acc, ull a, ull b) {
    asm("fma.rn.f32x2 %0, %1, %2, %0;" : "+l"(acc) : "l"(a), "l"(b));
}
__device__ __forceinline__ void fadd2(ull& acc, ull a) {
    asm("add.rn.f32x2 %0, %1, %0;" : "+l"(acc) : "l"(a));
}
__device__ __forceinline__ float2 up2(ull v) {
    float2 f;
    asm("mov.b64 {%0, %1}, %2;" : "=f"(f.x), "=f"(f.y) : "l"(v));
    return f;
}
__device__ __forceinline__ ull splat(float v) {
    ull r;
    asm("mov.b64 %0, {%1, %1};" : "=l"(r) : "f"(v));
    return r;
}
__device__ __forceinline__ __half2 geth2(const uint4& v, int p) {
    unsigned u = (&v.x)[p];
    return *reinterpret_cast<const __half2*>(&u);
}

// K1 v11 = round-12 core with a BARRIER-FREE main loop: the whole chunk's x
// (up to 14 j) is preloaded into smem once at kernel start (one
// __syncthreads total), so the 52-56-stage loop has ZERO CTA barriers —
// warps are fully decoupled (drift bounded only by their private 5-stage
// cp.async W rings). Previously 7 barrier pairs/CTA re-coupled all 8 warps
// every 8 stages, turning per-warp DRAM jitter into CTA-wide wait.
// smem: wbuf 40 KB + xs 63 KB = 103 KB/CTA (2 CTAs = 206 KB, fits).
__global__ void __launch_bounds__(256, 2)
k1(const float* __restrict__ x, const float* __restrict__ Wt) {
    const int w     = threadIdx.x >> 5;    // warp 0..7 -> k-slice [w*32, w*32+32)
    const int lane  = threadIdx.x & 31;
    const int kgl   = lane & 7;            // 4-k group within warp slice
    const int bg    = lane >> 3;           // 0..3 -> 8 b's
    const int chunk = blockIdx.x;          // 0..147
    const int kq    = blockIdx.y;          // 0..3
    const int j0    = (chunk * NN) / NCH1;
    const int j1    = ((chunk + 1) * NN) / NCH1;
    const int nst   = 4 * (j1 - j0);       // 52 or 56 stages

    __shared__ __align__(16) float wbuf[5][8][256];   // 40 KB W ring (warp-sliced)
    __shared__ __align__(16) float xs[14][32][36];    // 63 KB whole-chunk x (transposed, padded)

    const int cr = lane >> 2;
    const int cc = (lane & 3) * 8;

    ull pol;   // read-once W: evict-first so u stays resident in L2
    asm("createpolicy.fractional.L2::evict_first.b64 %0, 1.0;" : "=l"(pol));

    auto issue_stage = [&](int g) {
        const int jg = j0 + (g >> 2);
        const int ibase = (g & 3) * 8;
        const float* src = Wt + (size_t)jg * (IL * KK) + (size_t)(ibase + cr) * KK
                         + kq * 256 + w * 32 + cc;
        unsigned dst = (unsigned)__cvta_generic_to_shared(&wbuf[g % 5][cr][w * 32 + cc]);
        asm volatile(
            "cp.async.cg.shared.global.L2::cache_hint [%0], [%1], 16, %2;\n\t"
            "cp.async.cg.shared.global.L2::cache_hint [%3], [%4], 16, %2;"
            :: "r"(dst), "l"(src), "l"(pol), "r"(dst + 16), "l"(src + 4) : "memory");
    };

    ull acc[4][4], s0[4][4];               // [k][b-pair] f32x2
#pragma unroll
    for (int k = 0; k < 4; k++)
#pragma unroll
        for (int bp = 0; bp < 4; bp++) { acc[k][bp] = 0ull; s0[k][bp] = 0ull; }

    // W pipeline first (async, overlaps the x staging LDGs below)
#pragma unroll
    for (int pg = 0; pg < 4; pg++) {
        issue_stage(pg);
        asm volatile("cp.async.commit_group;" ::: "memory");
    }

    // stage the WHOLE chunk's x once: 14 j x 32 i x 32 b (clamped read)
#pragma unroll 4
    for (int r = 0; r < 56; r++) {
        int idx = threadIdx.x + 256 * r;   // 14336 = 56*256 exactly
        int j = idx >> 10, rem = idx & 1023;
        int b = rem >> 5, i = rem & 31;
        int jj = j0 + j; if (jj > NN - 1) jj = NN - 1;
        xs[j][i][b] = x[((size_t)b * NN + jj) * IL + i];
    }
    __syncthreads();                       // the ONLY CTA barrier

    for (int g = 0; g < nst; g++) {        // stages: j-count x 4 i-blocks of 8
        // wait for THIS warp's stage-g slice only
        asm volatile("cp.async.wait_group 3;" ::: "memory");
        __syncwarp();

        const int jl = g >> 2;
        const int ib = (g & 3) * 8;
        const float (*wb)[256] = wbuf[g % 5];
#pragma unroll
        for (int ii = 0; ii < 8; ii++) {
            float4 wv = *reinterpret_cast<const float4*>(&wb[ii][w * 32 + kgl * 4]);
            ull ws0 = splat(wv.x), ws1 = splat(wv.y), ws2 = splat(wv.z), ws3 = splat(wv.w);
            ulonglong2 xu0 = *reinterpret_cast<const ulonglong2*>(&xs[jl][ib + ii][bg * 8]);
            ulonglong2 xu1 = *reinterpret_cast<const ulonglong2*>(&xs[jl][ib + ii][bg * 8 + 4]);
            ffma2(acc[0][0], ws0, xu0.x); ffma2(acc[0][1], ws0, xu0.y);
            ffma2(acc[0][2], ws0, xu1.x); ffma2(acc[0][3], ws0, xu1.y);
            ffma2(acc[1][0], ws1, xu0.x); ffma2(acc[1][1], ws1, xu0.y);
            ffma2(acc[1][2], ws1, xu1.x); ffma2(acc[1][3], ws1, xu1.y);
            ffma2(acc[2][0], ws2, xu0.x); ffma2(acc[2][1], ws2, xu0.y);
            ffma2(acc[2][2], ws2, xu1.x); ffma2(acc[2][3], ws2, xu1.y);
            ffma2(acc[3][0], ws3, xu0.x); ffma2(acc[3][1], ws3, xu0.y);
            ffma2(acc[3][2], ws3, xu1.x); ffma2(acc[3][3], ws3, xu1.y);
        }

        if ((g & 3) == 3) {
            // j complete: store u row (fp16), fold s0, reset acc
            const int jg = j0 + (g >> 2);
            const size_t kb = (size_t)kq * 256 + (size_t)(w * 32 + kgl * 4);
#pragma unroll
            for (int bp = 0; bp < 4; bp++) {
                float2 f0 = up2(acc[0][bp]), f1 = up2(acc[1][bp]);
                float2 f2 = up2(acc[2][bp]), f3 = up2(acc[3][bp]);
                const int be = bg * 8 + bp * 2;
                __half2 h0 = __floats2half2_rn(f0.x, f1.x);
                __half2 h1 = __floats2half2_rn(f2.x, f3.x);
                uint2 pk;
                pk.x = *reinterpret_cast<unsigned*>(&h0);
                pk.y = *reinterpret_cast<unsigned*>(&h1);
                *reinterpret_cast<uint2*>(g_uh + ((size_t)be * NN + jg) * KK + kb) = pk;
                h0 = __floats2half2_rn(f0.y, f1.y);
                h1 = __floats2half2_rn(f2.y, f3.y);
                pk.x = *reinterpret_cast<unsigned*>(&h0);
                pk.y = *reinterpret_cast<unsigned*>(&h1);
                *reinterpret_cast<uint2*>(g_uh + ((size_t)(be + 1) * NN + jg) * KK + kb) = pk;
#pragma unroll
                for (int k = 0; k < 4; k++) {
                    fadd2(s0[k][bp], acc[k][bp]);
                    acc[k][bp] = 0ull;
                }
            }
        }

        if (g + 4 < nst) issue_stage(g + 4);
        asm volatile("cp.async.commit_group;" ::: "memory");
    }

    // s0 partial store (softmax(0) coupling = 1/32)
    const float scl = 1.0f / 32.0f;
    const size_t kb = (size_t)kq * 256 + (size_t)(w * 32 + kgl * 4);
#pragma unroll
    for (int bp = 0; bp < 4; bp++) {
        float2 f0 = up2(s0[0][bp]), f1 = up2(s0[1][bp]);
        float2 f2 = up2(s0[2][bp]), f3 = up2(s0[3][bp]);
        const int be = bg * 8 + bp * 2;
        *reinterpret_cast<float4*>(g_s0p + ((size_t)be * NCH1 + chunk) * KK + kb) =
            make_float4(f0.x * scl, f1.x * scl, f2.x * scl, f3.x * scl);
        *reinterpret_cast<float4*>(g_s0p + ((size_t)(be + 1) * NCH1 + chunk) * KK + kb) =
            make_float4(f0.y * scl, f1.y * scl, f2.y * scl, f3.y * scl);
    }
}

// Routing pass (round-15 version: PCH=32, every warp exactly 8 j — balanced;
// no-max softmax, FFMA2 accumulation). Lane t's uint4 group q covers
// k = 8t+256q+e, all in capsule c_q = (t>>2)+8q; quad shfl completes each
// logit, shfl xor 4/8/16 spans the 32 capsules.
template <int NP>
__global__ void __launch_bounds__(256, 2)
k_pass(const float* __restrict__ vin0, const float* __restrict__ vin1,
       float* __restrict__ sp) {
    const int b = blockIdx.y;
    const int w = threadIdx.x >> 5;
    const int t = threadIdx.x & 31;

    __shared__ float red[8][1032];     // CTA reduction (16B-aligned rows)

    // v as half2 registers at the u k-mapping (NP==2 folds v0+v1)
    __half2 vh[16];
#pragma unroll
    for (int q = 0; q < 4; q++) {
        float4 a = *reinterpret_cast<const float4*>(vin0 + (size_t)b * KK + 8 * t + 256 * q);
        float4 c4 = *reinterpret_cast<const float4*>(vin0 + (size_t)b * KK + 8 * t + 256 * q + 4);
        if (NP == 2) {
            float4 a1 = *reinterpret_cast<const float4*>(vin1 + (size_t)b * KK + 8 * t + 256 * q);
            float4 c1 = *reinterpret_cast<const float4*>(vin1 + (size_t)b * KK + 8 * t + 256 * q + 4);
            a.x += a1.x; a.y += a1.y; a.z += a1.z; a.w += a1.w;
            c4.x += c1.x; c4.y += c1.y; c4.z += c1.z; c4.w += c1.w;
        }
        vh[q * 4 + 0] = __floats2half2_rn(a.x, a.y);
        vh[q * 4 + 1] = __floats2half2_rn(a.z, a.w);
        vh[q * 4 + 2] = __floats2half2_rn(c4.x, c4.y);
        vh[q * 4 + 3] = __floats2half2_rn(c4.z, c4.w);
    }

    ull sacc2[16];                     // packed f32x2 s accumulators
#pragma unroll
    for (int l = 0; l < 16; l++) sacc2[l] = 0ull;

    const int jbase = blockIdx.x * 64 + w * 8;   // 8 warps x 8 j = 64 j / CTA
    const uint4* up = reinterpret_cast<const uint4*>(g_uh + ((size_t)b * NN + jbase) * KK);

    uint4 raw0[4], raw1[4];
#pragma unroll
    for (int q = 0; q < 4; q++) raw0[q] = up[q * 32 + t];          // j0
#pragma unroll
    for (int q = 0; q < 4; q++) raw1[q] = up[128 + q * 32 + t];    // j1

    for (int jb = 0; jb < 8; jb += 2) {
        // free raw0 early: copy, then prefetch j+2 into it
        uint4 cpy0[4];
#pragma unroll
        for (int q = 0; q < 4; q++) cpy0[q] = raw0[q];
        if (jb + 2 < 8) {
#pragma unroll
            for (int q = 0; q < 4; q++) raw0[q] = up[(jb + 2) * 128 + q * 32 + t];
        }

        // logits for both rows (HFMA2 dot), interleaved
        float d0[4], d1[4];
#pragma unroll
        for (int q = 0; q < 4; q++) {
            __half2 a0 = __float2half2_rn(0.f), a1 = __float2half2_rn(0.f);
#pragma unroll
            for (int p = 0; p < 4; p++) {
                a0 = __hfma2(geth2(cpy0[q], p), vh[q * 4 + p], a0);
                a1 = __hfma2(geth2(raw1[q], p), vh[q * 4 + p], a1);
            }
            float2 f0 = __half22float2(a0), f1 = __half22float2(a1);
            d0[q] = f0.x + f0.y;
            d1[q] = f1.x + f1.y;
            d0[q] += __shfl_xor_sync(0xffffffffu, d0[q], 1);
            d1[q] += __shfl_xor_sync(0xffffffffu, d1[q], 1);
            d0[q] += __shfl_xor_sync(0xffffffffu, d0[q], 2);
            d1[q] += __shfl_xor_sync(0xffffffffu, d1[q], 2);
        }

        // softmax over 32 capsules WITHOUT max-subtraction (|d| is O(1))
        float ce0[4], ce1[4];
#pragma unroll
        for (int q = 0; q < 4; q++) {
            ce0[q] = __expf(d0[q]);
            ce1[q] = __expf(d1[q]);
        }
        float Z0 = (ce0[0] + ce0[1]) + (ce0[2] + ce0[3]);
        float Z1 = (ce1[0] + ce1[1]) + (ce1[2] + ce1[3]);
        Z0 += __shfl_xor_sync(0xffffffffu, Z0, 4);
        Z1 += __shfl_xor_sync(0xffffffffu, Z1, 4);
        Z0 += __shfl_xor_sync(0xffffffffu, Z0, 8);
        Z1 += __shfl_xor_sync(0xffffffffu, Z1, 8);
        Z0 += __shfl_xor_sync(0xffffffffu, Z0, 16);
        Z1 += __shfl_xor_sync(0xffffffffu, Z1, 16);
        const float i0 = __fdividef(1.0f, Z0);
        const float i1 = __fdividef(1.0f, Z1);

        // accumulate both rows: coupling splat + packed FFMA2
#pragma unroll
        for (int q = 0; q < 4; q++) {
            ull cs0 = splat(ce0[q] * i0);
            ull cs1 = splat(ce1[q] * i1);
#pragma unroll
            for (int p = 0; p < 4; p++) {
                float2 f = __half22float2(geth2(cpy0[q], p));
                ffma2(sacc2[q * 4 + p], cs0, *reinterpret_cast<ull*>(&f));
                f = __half22float2(geth2(raw1[q], p));
                ffma2(sacc2[q * 4 + p], cs1, *reinterpret_cast<ull*>(&f));
            }
        }

        // raw1 now free: prefetch j+3
        if (jb + 3 < 8) {
#pragma unroll
            for (int q = 0; q < 4; q++) raw1[q] = up[(jb + 3) * 128 + q * 32 + t];
        }
    }

    // CTA reduction across the 8 warps (natural k layout)
#pragma unroll
    for (int q = 0; q < 4; q++) {
        float2 p0 = up2(sacc2[q * 4 + 0]), p1 = up2(sacc2[q * 4 + 1]);
        float2 p2 = up2(sacc2[q * 4 + 2]), p3 = up2(sacc2[q * 4 + 3]);
        *reinterpret_cast<float4*>(&red[w][8 * t + 256 * q])     =
            make_float4(p0.x, p0.y, p1.x, p1.y);
        *reinterpret_cast<float4*>(&red[w][8 * t + 256 * q + 4]) =
            make_float4(p2.x, p2.y, p3.x, p3.y);
    }
    __syncthreads();

    float4 s = make_float4(0.f, 0.f, 0.f, 0.f);
#pragma unroll
    for (int ww = 0; ww < 8; ww++) {
        float4 p = *reinterpret_cast<const float4*>(&red[ww][4 * threadIdx.x]);
        s.x += p.x; s.y += p.y; s.z += p.z; s.w += p.w;
    }
    *reinterpret_cast<float4*>(sp + ((size_t)b * PCH + blockIdx.x) * KK + 4 * threadIdx.x) = s;
}

// Finalize: reduce NCH chunk partials + biases, squash -> v.
// One CTA (8 warps) per (b,c) for memory-level parallelism on the reduction.
template <int NCH>
__global__ void __launch_bounds__(256)
k_fin(const float* __restrict__ sp, const float* __restrict__ biases,
      float* __restrict__ vout) {
    const int bc = blockIdx.x;
    const int b = bc >> 5, c = bc & 31;
    const int w = threadIdx.x >> 5, lane = threadIdx.x & 31;

    float s = 0.f;
    const float* p = sp + (size_t)b * NCH * KK + c * LL + lane;
#pragma unroll 8
    for (int n = w; n < NCH; n += 8) s += p[(size_t)n * KK];

    __shared__ float red[8][32];
    red[w][lane] = s;
    __syncthreads();

    if (w == 0) {
        float v = biases[c * LL + lane];
#pragma unroll
        for (int ww = 0; ww < 8; ww++) v += red[ww][lane];
        float n2 = v * v;
#pragma unroll
        for (int o = 16; o; o >>= 1) n2 += __shfl_xor_sync(0xffffffffu, n2, o);
        const float nn = sqrtf(n2);
        const float f = n2 / (1.0f + n2) / (nn + 1e-7f);   // squash factor
        vout[(size_t)b * KK + c * LL + lane] = f * v;
    }
}

extern "C" void kernel_launch(void* const* d_in, const int* in_sizes, int n_in,
                              void* d_out, int out_size) {
    const float* x      = (const float*)d_in[0];  // [32,8,8,32,32] = [B,N,iL]
    const float* Wt     = (const float*)d_in[1];  // [2048,32,1024]
    const float* biases = (const float*)d_in[2];  // [32,32]
    float* out = (float*)d_out;                   // [32,32,32]

    float *s0p, *sp, *v0, *v1;
    cudaGetSymbolAddress((void**)&s0p, g_s0p);
    cudaGetSymbolAddress((void**)&sp,  g_sp);
    cudaGetSymbolAddress((void**)&v0,  g_v0);
    cudaGetSymbolAddress((void**)&v1,  g_v1);

    // 6 launches, no dummies; balanced PCH=32 passes.
    k1<<<dim3(NCH1, 4), 256>>>(x, Wt);                   // 0
    k_fin<NCH1><<<BB * CC, 256>>>(s0p, biases, v0);      // 1
    k_pass<1><<<dim3(PCH, BB), 256>>>(v0, v0, sp);       // 2
    k_fin<PCH><<<BB * CC, 256>>>(sp, biases, v1);        // 3
    k_pass<2><<<dim3(PCH, BB), 256>>>(v0, v1, sp);       // 4
    k_fin<PCH><<<BB * CC, 256>>>(sp, biases, out);       // 5
}